// round 4
// baseline (speedup 1.0000x reference)
#include <cuda_runtime.h>
#include <cuda_bf16.h>
#include <cstdint>

// R4: identical logic to R2/R3 candidate (never executed due to infra failures).
// Chunked linear-scan EMA + segment scatter, with on-device input classification.

// Problem shapes (fixed by the dataset)
#define BB 4
#define LL 4096
#define MM 2048
#define DD 2048
#define EPSV 1e-4f

#define TC 32              // timesteps per chunk
#define NCH (MM / TC)      // 64 chunks
#define DB 512             // channels per block slice (128 threads x float4)
#define NDS (DD / DB)      // 4 d-slices

// Input-kind classification
#define K_BYTE 0   // 1-byte bool
#define K_WORD 1   // 4-byte int bool
#define K_FBOOL 2  // float32 0.0/1.0 bool
#define K_PROB 3   // float32 probabilities

// Scratch (static device arrays; no allocation allowed)
__device__ float g_p[BB * MM];
__device__ float g_a[BB * MM];
__device__ int   g_bpos[BB * (MM + 1)];
__device__ float g_A[BB * NCH];
__device__ float g_B[BB * NCH * DD];
__device__ float g_Hin[BB * NCH * DD];

__device__ __forceinline__ void classify(const uint8_t* p, int* kind, int* hz) {
    const uint32_t* w = (const uint32_t*)p;
    bool bb = true, wb = true, fb = true;
    int zb = 0, zw = 0;
    for (int i = 0; i < 64; i++) {
        const uint32_t v = w[i];
        if (v == 0u) zw = 1;
        if (v > 1u) wb = false;
        if (v != 0u && v != 0x3F800000u) fb = false;
#pragma unroll
        for (int k = 0; k < 4; k++) {
            const uint32_t bv = (v >> (8 * k)) & 0xFFu;
            if (bv > 1u) bb = false;
            if (bv == 0u) zb = 1;
        }
    }
    if (wb)      { *kind = K_WORD;  *hz = zw; }
    else if (fb) { *kind = K_FBOOL; *hz = zw; }
    else if (bb) { *kind = K_BYTE;  *hz = zb; }
    else         { *kind = K_PROB;  *hz = 0;  }
}

__device__ __forceinline__ int get_mask(const uint8_t* p, int kind, int l) {
    if (kind == K_BYTE) return p[l] != 0;
    return ((const uint32_t*)p)[l] != 0u;   // K_WORD or K_FBOOL
}

// ---------------------------------------------------------------------------
// K0: identify inputs, then per batch: block-scan boundary_mask, gather p
// (stable-sort order: boundary tokens first, in order), build segment table
// bpos, and per-chunk decay products A.
// ---------------------------------------------------------------------------
__global__ void k0_prep(const uint8_t* s0, const uint8_t* s1,
                        const uint8_t* s2, int ns) {
    const int b = blockIdx.x;
    const int tid = threadIdx.x;              // 1024 threads, 4 elems each
    __shared__ int wsum[32];
    __shared__ int s_numB;
    __shared__ int s_pi, s_bi, s_bkind;

    if (tid == 0) {
        const uint8_t* s[3] = { s0, s1, s2 };
        int kind[3], hz[3];
        for (int j = 0; j < ns; j++) classify(s[j], &kind[j], &hz[j]);
        int pi = -1;
        for (int j = 0; j < ns; j++) if (kind[j] == K_PROB) { pi = j; break; }
        if (pi < 0) pi = 0;                   // fallback: dict order
        int bi = -1;
        for (int j = 0; j < ns; j++)
            if (j != pi && kind[j] != K_PROB && hz[j]) { bi = j; break; }
        if (bi < 0)
            for (int j = 0; j < ns; j++)
                if (j != pi && kind[j] != K_PROB) { bi = j; break; }
        if (bi < 0) bi = (pi == 1) ? 2 : 1;   // fallback
        s_pi = pi; s_bi = bi; s_bkind = kind[bi];
    }
    __syncthreads();

    const uint8_t* sel[3] = { s0, s1, s2 };
    const float* prob = (const float*)sel[s_pi];
    const uint8_t* bm = sel[s_bi];
    const int bkind = s_bkind;

    const int l0 = tid * 4;
    int m[4];
    int s = 0;
#pragma unroll
    for (int j = 0; j < 4; j++) {
        m[j] = get_mask(bm, bkind, b * LL + l0 + j);
        s += m[j];
    }

    const int lane = tid & 31, wid = tid >> 5;
    int incl = s;
#pragma unroll
    for (int o = 1; o < 32; o <<= 1) {
        int v = __shfl_up_sync(0xffffffffu, incl, o);
        if (lane >= o) incl += v;
    }
    if (lane == 31) wsum[wid] = incl;
    __syncthreads();
    if (wid == 0) {
        int v = wsum[lane];
#pragma unroll
        for (int o = 1; o < 32; o <<= 1) {
            int u = __shfl_up_sync(0xffffffffu, v, o);
            if (lane >= o) v += u;
        }
        wsum[lane] = v;
        if (lane == 31) s_numB = v;
    }
    __syncthreads();

    const int excl_w = (wid == 0) ? 0 : wsum[wid - 1];
    const int excl_t = excl_w + (incl - s);
    const int numB = s_numB;

    int run = excl_t;
#pragma unroll
    for (int j = 0; j < 4; j++) {
        const int l = l0 + j;
        const int isb = m[j];
        run += isb;                                   // inclusive count at l
        const int r = isb ? (run - 1) : (numB + (l - run));
        if (r < MM) {
            float p = prob[(size_t)b * LL + l];
            p = fminf(fmaxf(p, EPSV), 1.0f - EPSV);
            g_p[b * MM + r] = p;
            g_a[b * MM + r] = 1.0f - p;
            if (isb) g_bpos[b * (MM + 1) + r] = l;
        }
    }
    // Tail: empty segments for ranks >= numB, sentinel at MM.
    for (int r = numB + tid; r <= MM; r += blockDim.x)
        g_bpos[b * (MM + 1) + r] = LL;

    __syncthreads();  // g_p/g_a writes visible block-wide

    for (int ch = tid; ch < NCH; ch += blockDim.x) {
        float A = 1.0f;
#pragma unroll
        for (int t = 0; t < TC; t++) A *= g_a[b * MM + ch * TC + t];
        g_A[b * NCH + ch] = A;
    }
}

// ---------------------------------------------------------------------------
// K1: chunk-local recurrence with h=0 -> per-chunk carry vectors g_B.
// ---------------------------------------------------------------------------
__global__ void __launch_bounds__(128)
k1_partials(const float* __restrict__ hid) {
    const int ch = blockIdx.x, ds = blockIdx.y, b = blockIdx.z;
    const int tid = threadIdx.x;

    __shared__ float sp[TC], sa[TC];
    if (tid < TC) {
        sp[tid] = g_p[b * MM + ch * TC + tid];
        sa[tid] = g_a[b * MM + ch * TC + tid];
    }
    __syncthreads();

    const int c0 = ds * DB + tid * 4;
    const float4* src =
        (const float4*)(hid + ((size_t)(b * MM + ch * TC)) * DD + c0);
    const int rs = DD / 4;

    float4 h = make_float4(0.f, 0.f, 0.f, 0.f);
#pragma unroll
    for (int t = 0; t < TC; t++) {
        const float4 x = src[(size_t)t * rs];
        const float p = sp[t], a = sa[t];
        h.x = fmaf(a, h.x, p * x.x);
        h.y = fmaf(a, h.y, p * x.y);
        h.z = fmaf(a, h.z, p * x.z);
        h.w = fmaf(a, h.w, p * x.w);
    }
    *((float4*)&g_B[(size_t)(b * NCH + ch) * DD + c0]) = h;
}

// ---------------------------------------------------------------------------
// K2: sequential combine across the 64 chunks -> exclusive chunk inputs g_Hin.
// ---------------------------------------------------------------------------
__global__ void k2_combine() {
    const int idx = blockIdx.x * blockDim.x + threadIdx.x;   // BB*DD threads
    const int b = idx / DD, d = idx % DD;
    float h = 0.f;
#pragma unroll 4
    for (int c = 0; c < NCH; c++) {
        g_Hin[(size_t)(b * NCH + c) * DD + d] = h;
        h = fmaf(g_A[b * NCH + c], h, g_B[(size_t)(b * NCH + c) * DD + d]);
    }
}

// ---------------------------------------------------------------------------
// K3: recompute chunk-local scan seeded with g_Hin; scatter each state to its
// output segment [bpos[t], bpos[t+1]).
// ---------------------------------------------------------------------------
__global__ void __launch_bounds__(128)
k3_final(const float* __restrict__ hid, float* __restrict__ out) {
    const int ch = blockIdx.x, ds = blockIdx.y, b = blockIdx.z;
    const int tid = threadIdx.x;

    __shared__ float sp[TC], sa[TC];
    __shared__ int sbp[TC + 1];
    if (tid < TC) {
        sp[tid] = g_p[b * MM + ch * TC + tid];
        sa[tid] = g_a[b * MM + ch * TC + tid];
    }
    if (tid <= TC) sbp[tid] = g_bpos[b * (MM + 1) + ch * TC + tid];
    __syncthreads();

    const int c0 = ds * DB + tid * 4;
    const float4* src =
        (const float4*)(hid + ((size_t)(b * MM + ch * TC)) * DD + c0);
    const int rs = DD / 4;

    float4 h = *((const float4*)&g_Hin[(size_t)(b * NCH + ch) * DD + c0]);
    float4* outbase = (float4*)(out + ((size_t)b * LL) * DD + c0);

#pragma unroll
    for (int t = 0; t < TC; t++) {
        const float4 x = src[(size_t)t * rs];
        const float p = sp[t], a = sa[t];
        h.x = fmaf(a, h.x, p * x.x);
        h.y = fmaf(a, h.y, p * x.y);
        h.z = fmaf(a, h.z, p * x.z);
        h.w = fmaf(a, h.w, p * x.w);
        const int l0 = sbp[t], l1 = sbp[t + 1];
        for (int l = l0; l < l1; l++) outbase[(size_t)l * rs] = h;
    }
}

// ---------------------------------------------------------------------------
extern "C" void kernel_launch(void* const* d_in, const int* in_sizes, int n_in,
                              void* d_out, int out_size) {
    // hidden_states = input with the largest element count (B*M*D = 16.7M)
    int hid_i = 0;
    for (int i = 1; i < n_in; i++)
        if (in_sizes[i] > in_sizes[hid_i]) hid_i = i;
    const float* hid = (const float*)d_in[hid_i];

    // remaining (small) inputs in original order; k0 classifies them on-device
    const void* sm[3] = { nullptr, nullptr, nullptr };
    int ns = 0;
    for (int i = 0; i < n_in && ns < 3; i++)
        if (i != hid_i) sm[ns++] = d_in[i];
    if (ns == 1) { sm[1] = sm[0]; sm[2] = sm[0]; }
    if (ns == 2) { sm[2] = sm[1]; }

    float* out = (float*)d_out;   // (B, L, D) f32

    k0_prep<<<BB, 1024>>>((const uint8_t*)sm[0], (const uint8_t*)sm[1],
                          (const uint8_t*)sm[2], ns);
    dim3 g(NCH, NDS, BB);
    k1_partials<<<g, 128>>>(hid);
    k2_combine<<<(BB * DD) / 256, 256>>>();
    k3_final<<<g, 128>>>(hid, out);
}